// round 2
// baseline (speedup 1.0000x reference)
#include <cuda_runtime.h>
#include <cstdint>

typedef unsigned long long ull;

#define Bq 4
#define Sq 4096
#define Eq 1024
#define Hq 64

// Scratch for projected Q, K, V (allocation-free rule: __device__ globals)
__device__ float g_Q[Bq * Sq * Hq];
__device__ float g_K[Bq * Sq * Hq];
__device__ float g_V[Bq * Sq * Hq];

// ---- packed f32x2 helpers (FFMA2 — ptxas never emits this from C++) ----
__device__ __forceinline__ void ffma2(ull& a, ull x, ull y) {
    asm("fma.rn.f32x2 %0, %1, %2, %0;" : "+l"(a) : "l"(x), "l"(y));
}
__device__ __forceinline__ ull fmul2(ull x, ull y) {
    ull r; asm("mul.rn.f32x2 %0, %1, %2;" : "=l"(r) : "l"(x), "l"(y)); return r;
}
__device__ __forceinline__ ull pack2(float lo, float hi) {
    ull r; asm("mov.b64 %0, {%1, %2};" : "=l"(r) : "f"(lo), "f"(hi)); return r;
}
__device__ __forceinline__ float lo2(ull v) { return __uint_as_float((unsigned)v); }
__device__ __forceinline__ float hi2(ull v) { return __uint_as_float((unsigned)(v >> 32)); }

// ============================================================================
// Kernel 1: fused QKV projection GEMM.
// M=16384, K=1024, N=64 per weight. Grid (128 m-tiles, 3 weights), 256 thr.
// Block tile 128x64, k-chunk 32. FFMA2 pairs along M (xs stored transposed
// [k][row] so row-pairs are contiguous 8B loads).
// ============================================================================
__global__ __launch_bounds__(256) void qkv_kernel(
    const float* __restrict__ x, const float* __restrict__ Wq,
    const float* __restrict__ Wk, const float* __restrict__ Wv)
{
    __shared__ float xs[32][132];   // [k][row], pad 132 to reduce conflicts
    __shared__ float ws[32][64];    // [k][col]

    const int w = blockIdx.y;
    const float* W = (w == 0) ? Wq : (w == 1) ? Wk : Wv;
    float* out = (w == 0) ? g_Q : (w == 1) ? g_K : g_V;

    const int tid = threadIdx.x;
    const int tx = tid & 15;        // col group: cols tx*4 .. tx*4+3
    const int ty = tid >> 4;        // row group: rows ty*8 .. ty*8+7 (4 pairs)
    const int m0 = blockIdx.x * 128;

    ull acc[4][4] = {};             // [row-pair][col], each ull = (row even, row odd)

    for (int k0 = 0; k0 < Eq; k0 += 32) {
        // load x tile 128x32 (transposed into xs[k][row])
        #pragma unroll
        for (int it = 0; it < 4; it++) {
            int slot = tid + it * 256;      // 0..1023 float4 slots (128 rows x 8)
            int r = slot >> 3;
            int c4 = slot & 7;
            float4 v = *(const float4*)&x[(size_t)(m0 + r) * Eq + k0 + c4 * 4];
            xs[c4 * 4 + 0][r] = v.x;
            xs[c4 * 4 + 1][r] = v.y;
            xs[c4 * 4 + 2][r] = v.z;
            xs[c4 * 4 + 3][r] = v.w;
        }
        // load W chunk 32x64 (direct layout)
        #pragma unroll
        for (int it = 0; it < 2; it++) {
            int slot = tid + it * 256;      // 0..511 float4 slots (32 rows x 16)
            int r = slot >> 4;
            int c4 = slot & 15;
            *(float4*)&ws[r][c4 * 4] = *(const float4*)&W[(size_t)(k0 + r) * Hq + c4 * 4];
        }
        __syncthreads();

        #pragma unroll 8
        for (int kk = 0; kk < 32; kk++) {
            ull a2[4];
            #pragma unroll
            for (int i = 0; i < 4; i++)
                a2[i] = *(const ull*)&xs[kk][ty * 8 + 2 * i];   // (row, row+1) pair
            float4 bv = *(const float4*)&ws[kk][tx * 4];
            ull b2[4] = { pack2(bv.x, bv.x), pack2(bv.y, bv.y),
                          pack2(bv.z, bv.z), pack2(bv.w, bv.w) };
            #pragma unroll
            for (int i = 0; i < 4; i++)
                #pragma unroll
                for (int j = 0; j < 4; j++)
                    ffma2(acc[i][j], a2[i], b2[j]);
        }
        __syncthreads();
    }

    #pragma unroll
    for (int i = 0; i < 4; i++) {
        int r = m0 + ty * 8 + 2 * i;
        float4 v0 = { lo2(acc[i][0]), lo2(acc[i][1]), lo2(acc[i][2]), lo2(acc[i][3]) };
        float4 v1 = { hi2(acc[i][0]), hi2(acc[i][1]), hi2(acc[i][2]), hi2(acc[i][3]) };
        *(float4*)&out[(size_t)r * Hq + tx * 4] = v0;
        *(float4*)&out[(size_t)(r + 1) * Hq + tx * 4] = v1;
    }
}

// ============================================================================
// Kernel 2: causal flash attention, fp32, online softmax.
// Br = Bc = 64, 256 threads (16x16 map, each thread owns a 4x4 score tile).
// Each block handles TWO q-tiles: qt and 63-qt -> exactly 65 kv-iterations
// per block (perfect causal load balance). Grid (32, 4) = 128 blocks.
// FFMA2 pairs: QK^T along head dim (contiguous), PV along output head dim
// (contiguous in V rows).
// ============================================================================
__global__ __launch_bounds__(256, 1) void attn_kernel(float* __restrict__ out)
{
    extern __shared__ float sm[];
    float* Qs   = sm;                 // 64 x 68
    float* Ks   = Qs + 64 * 68;       // 64 x 68
    float* Vs   = Ks + 64 * 68;       // 64 x 68
    float* Ps   = Vs + 64 * 68;       // 64 x 68 (scores / probs)
    float* mrow = Ps + 64 * 68;       // 64
    float* lrow = mrow + 64;          // 64
    float* frow = lrow + 64;          // 64

    const int tid  = threadIdx.x;
    const int tx   = tid & 15;        // cols tx*4 .. +3
    const int ty   = tid >> 4;        // rows ty*4 .. +3
    const int b    = blockIdx.y;
    const int wid  = tid >> 5;
    const int lane = tid & 31;

    #pragma unroll 1
    for (int half = 0; half < 2; half++) {
        const int qt = (half == 0) ? (int)blockIdx.x : 63 - (int)blockIdx.x;

        __syncthreads();   // protect Qs / stats vs previous half's epilogue reads

        const float* Qg = g_Q + ((size_t)b * Sq + (size_t)qt * 64) * Hq;
        #pragma unroll
        for (int it = 0; it < 4; it++) {
            int slot = tid + it * 256;          // 64 rows x 16 float4
            int r = slot >> 4, c4 = slot & 15;
            *(float4*)&Qs[r * 68 + c4 * 4] = *(const float4*)&Qg[r * 64 + c4 * 4];
        }
        if (tid < 64) { mrow[tid] = -1e30f; lrow[tid] = 0.0f; }
        ull o2[4][2] = {};   // [row i][h-pair]: (h even, h odd) partial outputs
        __syncthreads();

        for (int kt = 0; kt <= qt; kt++) {
            const float* Kg = g_K + ((size_t)b * Sq + (size_t)kt * 64) * Hq;
            const float* Vg = g_V + ((size_t)b * Sq + (size_t)kt * 64) * Hq;
            #pragma unroll
            for (int it = 0; it < 4; it++) {
                int slot = tid + it * 256;
                int r = slot >> 4, c4 = slot & 15;
                *(float4*)&Ks[r * 68 + c4 * 4] = *(const float4*)&Kg[r * 64 + c4 * 4];
                *(float4*)&Vs[r * 68 + c4 * 4] = *(const float4*)&Vg[r * 64 + c4 * 4];
            }
            __syncthreads();

            // ---- S = Q K^T (FFMA2 paired along head dim) ----
            ull acc[4][4] = {};
            #pragma unroll 4
            for (int h = 0; h < 64; h += 4) {
                double2 qd[4], kd[4];
                #pragma unroll
                for (int i = 0; i < 4; i++)
                    qd[i] = *(const double2*)&Qs[(ty * 4 + i) * 68 + h];
                #pragma unroll
                for (int j = 0; j < 4; j++)
                    kd[j] = *(const double2*)&Ks[(tx * 4 + j) * 68 + h];
                #pragma unroll
                for (int i = 0; i < 4; i++)
                    #pragma unroll
                    for (int j = 0; j < 4; j++) {
                        ffma2(acc[i][j], (ull)__double_as_longlong(qd[i].x),
                                          (ull)__double_as_longlong(kd[j].x));
                        ffma2(acc[i][j], (ull)__double_as_longlong(qd[i].y),
                                          (ull)__double_as_longlong(kd[j].y));
                    }
            }

            // ---- scale + causal mask + stage scores ----
            #pragma unroll
            for (int i = 0; i < 4; i++) {
                int gi = qt * 64 + ty * 4 + i;
                #pragma unroll
                for (int j = 0; j < 4; j++) {
                    int gj = kt * 64 + tx * 4 + j;
                    float sv = (lo2(acc[i][j]) + hi2(acc[i][j])) * 0.125f;  // H^-0.5
                    if (gj > gi) sv = -1e30f;
                    Ps[(ty * 4 + i) * 68 + tx * 4 + j] = sv;
                }
            }
            __syncthreads();

            // ---- online softmax: warp w owns rows 8w..8w+7 ----
            #pragma unroll 1
            for (int rr = 0; rr < 8; rr++) {
                int r = wid * 8 + rr;
                float s0 = Ps[r * 68 + lane];
                float s1 = Ps[r * 68 + 32 + lane];
                float mx = fmaxf(s0, s1);
                #pragma unroll
                for (int off = 16; off > 0; off >>= 1)
                    mx = fmaxf(mx, __shfl_xor_sync(0xffffffffu, mx, off));
                float mold = mrow[r];
                float mnew = fmaxf(mold, mx);
                float p0 = __expf(s0 - mnew);
                float p1 = __expf(s1 - mnew);
                Ps[r * 68 + lane]      = p0;
                Ps[r * 68 + 32 + lane] = p1;
                float ps = p0 + p1;
                #pragma unroll
                for (int off = 16; off > 0; off >>= 1)
                    ps += __shfl_xor_sync(0xffffffffu, ps, off);
                if (lane == 0) {
                    float f = __expf(mold - mnew);
                    frow[r] = f;
                    lrow[r] = lrow[r] * f + ps;
                    mrow[r] = mnew;
                }
            }
            __syncthreads();

            // ---- rescale O, accumulate O += P V (FFMA2 paired along H) ----
            #pragma unroll
            for (int i = 0; i < 4; i++) {
                float f = frow[ty * 4 + i];
                ull f2 = pack2(f, f);
                o2[i][0] = fmul2(o2[i][0], f2);
                o2[i][1] = fmul2(o2[i][1], f2);
            }
            #pragma unroll 8
            for (int j = 0; j < 64; j++) {
                double2 vv = *(const double2*)&Vs[j * 68 + tx * 4];
                ull v0 = (ull)__double_as_longlong(vv.x);   // V[j][tx*4 + {0,1}]
                ull v1 = (ull)__double_as_longlong(vv.y);   // V[j][tx*4 + {2,3}]
                #pragma unroll
                for (int i = 0; i < 4; i++) {
                    float p = Ps[(ty * 4 + i) * 68 + j];
                    ull p2 = pack2(p, p);
                    ffma2(o2[i][0], p2, v0);
                    ffma2(o2[i][1], p2, v1);
                }
            }
            __syncthreads();
        }

        // ---- epilogue: O /= l, write out ----
        #pragma unroll
        for (int i = 0; i < 4; i++) {
            int r = ty * 4 + i;
            float inv = 1.0f / lrow[r];
            float4 res;
            res.x = lo2(o2[i][0]) * inv;
            res.y = hi2(o2[i][0]) * inv;
            res.z = lo2(o2[i][1]) * inv;
            res.w = hi2(o2[i][1]) * inv;
            *(float4*)&out[((size_t)b * Sq + (size_t)qt * 64 + r) * Hq + tx * 4] = res;
        }
    }
}

// ============================================================================
extern "C" void kernel_launch(void* const* d_in, const int* in_sizes, int n_in,
                              void* d_out, int out_size)
{
    const float* x  = (const float*)d_in[0];
    const float* Wq = (const float*)d_in[1];
    const float* Wk = (const float*)d_in[2];
    const float* Wv = (const float*)d_in[3];
    float* out = (float*)d_out;

    const int attn_smem = (4 * 64 * 68 + 3 * 64) * (int)sizeof(float);  // 70400 B
    cudaFuncSetAttribute(attn_kernel, cudaFuncAttributeMaxDynamicSharedMemorySize,
                         attn_smem);

    qkv_kernel<<<dim3(128, 3), 256>>>(x, Wq, Wk, Wv);
    attn_kernel<<<dim3(32, 4), 256, attn_smem>>>(out);
}

// round 4
// speedup vs baseline: 1.2324x; 1.2324x over previous
#include <cuda_runtime.h>
#include <cstdint>

typedef unsigned long long ull;

#define Bq 4
#define Sq 4096
#define Eq 1024
#define Hq 64

// Scratch for projected Q, K, V (allocation-free rule: __device__ globals)
__device__ float g_Q[Bq * Sq * Hq];
__device__ float g_K[Bq * Sq * Hq];
__device__ float g_V[Bq * Sq * Hq];

// ---- packed f32x2 helpers (FFMA2 — ptxas never emits this from C++) ----
__device__ __forceinline__ void ffma2(ull& a, ull x, ull y) {
    asm("fma.rn.f32x2 %0, %1, %2, %0;" : "+l"(a) : "l"(x), "l"(y));
}
__device__ __forceinline__ ull fmul2(ull x, ull y) {
    ull r; asm("mul.rn.f32x2 %0, %1, %2;" : "=l"(r) : "l"(x), "l"(y)); return r;
}
__device__ __forceinline__ ull pack2(float lo, float hi) {
    ull r; asm("mov.b64 %0, {%1, %2};" : "=l"(r) : "f"(lo), "f"(hi)); return r;
}
__device__ __forceinline__ float lo2(ull v) { return __uint_as_float((unsigned)v); }
__device__ __forceinline__ float hi2(ull v) { return __uint_as_float((unsigned)(v >> 32)); }

// ============================================================================
// Kernel 1: fused QKV projection GEMM (unchanged from R1 — ~150us, revisit
// with tcgen05 later).
// ============================================================================
__global__ __launch_bounds__(256) void qkv_kernel(
    const float* __restrict__ x, const float* __restrict__ Wq,
    const float* __restrict__ Wk, const float* __restrict__ Wv)
{
    __shared__ float xs[32][132];   // [k][row]
    __shared__ float ws[32][64];    // [k][col]

    const int w = blockIdx.y;
    const float* W = (w == 0) ? Wq : (w == 1) ? Wk : Wv;
    float* out = (w == 0) ? g_Q : (w == 1) ? g_K : g_V;

    const int tid = threadIdx.x;
    const int tx = tid & 15;
    const int ty = tid >> 4;
    const int m0 = blockIdx.x * 128;

    ull acc[4][4] = {};

    for (int k0 = 0; k0 < Eq; k0 += 32) {
        #pragma unroll
        for (int it = 0; it < 4; it++) {
            int slot = tid + it * 256;
            int r = slot >> 3;
            int c4 = slot & 7;
            float4 v = *(const float4*)&x[(size_t)(m0 + r) * Eq + k0 + c4 * 4];
            xs[c4 * 4 + 0][r] = v.x;
            xs[c4 * 4 + 1][r] = v.y;
            xs[c4 * 4 + 2][r] = v.z;
            xs[c4 * 4 + 3][r] = v.w;
        }
        #pragma unroll
        for (int it = 0; it < 2; it++) {
            int slot = tid + it * 256;
            int r = slot >> 4;
            int c4 = slot & 15;
            *(float4*)&ws[r][c4 * 4] = *(const float4*)&W[(size_t)(k0 + r) * Hq + c4 * 4];
        }
        __syncthreads();

        #pragma unroll 8
        for (int kk = 0; kk < 32; kk++) {
            ull a2[4];
            #pragma unroll
            for (int i = 0; i < 4; i++)
                a2[i] = *(const ull*)&xs[kk][ty * 8 + 2 * i];
            float4 bv = *(const float4*)&ws[kk][tx * 4];
            ull b2[4] = { pack2(bv.x, bv.x), pack2(bv.y, bv.y),
                          pack2(bv.z, bv.z), pack2(bv.w, bv.w) };
            #pragma unroll
            for (int i = 0; i < 4; i++)
                #pragma unroll
                for (int j = 0; j < 4; j++)
                    ffma2(acc[i][j], a2[i], b2[j]);
        }
        __syncthreads();
    }

    #pragma unroll
    for (int i = 0; i < 4; i++) {
        int r = m0 + ty * 8 + 2 * i;
        float4 v0 = { lo2(acc[i][0]), lo2(acc[i][1]), lo2(acc[i][2]), lo2(acc[i][3]) };
        float4 v1 = { hi2(acc[i][0]), hi2(acc[i][1]), hi2(acc[i][2]), hi2(acc[i][3]) };
        *(float4*)&out[(size_t)r * Hq + tx * 4] = v0;
        *(float4*)&out[(size_t)(r + 1) * Hq + tx * 4] = v1;
    }
}

// ============================================================================
// Kernel 2: causal flash attention, fp32.
// R2 rewrite: register softmax (scores/stats never hit smem), float4 PV,
// double-buffered K/V with register prefetch, 2 syncs per kv-iteration.
// Br = Bc = 64, 256 threads (16x16), each thread owns a 4x4 score tile.
// Block handles q-tiles qt and 63-qt -> 65 kv-iterations (balanced).
// ============================================================================
__global__ __launch_bounds__(256, 1) void attn_kernel(float* __restrict__ out)
{
    extern __shared__ float sm[];
    float* Qs = sm;                    // 64 x 68
    float* Ks = Qs + 64 * 68;          // 2 x 64 x 68 (double buffer)
    float* Vs = Ks + 2 * 64 * 68;      // 2 x 64 x 68
    float* Ps = Vs + 2 * 64 * 68;      // 64 x 68

    const int tid  = threadIdx.x;
    const int tx   = tid & 15;         // owns cols tx*4 .. +3
    const int ty   = tid >> 4;         // owns rows ty*4 .. +3
    const int b    = blockIdx.y;

    #pragma unroll 1
    for (int half = 0; half < 2; half++) {
        const int qt = (half == 0) ? (int)blockIdx.x : 63 - (int)blockIdx.x;

        __syncthreads();   // protect smem reuse vs previous half

        // load Q tile
        const float* Qg = g_Q + ((size_t)b * Sq + (size_t)qt * 64) * Hq;
        #pragma unroll
        for (int it = 0; it < 4; it++) {
            int slot = tid + it * 256;          // 64 rows x 16 float4
            int r = slot >> 4, c4 = slot & 15;
            *(float4*)&Qs[r * 68 + c4 * 4] = *(const float4*)&Qg[r * 64 + c4 * 4];
        }

        float m[4], l[4];
        #pragma unroll
        for (int i = 0; i < 4; i++) { m[i] = -1e30f; l[i] = 0.0f; }
        ull o2[4][2] = {};

        // prefetch kv-tile 0 into registers
        const float* Kbase = g_K + (size_t)b * Sq * Hq;
        const float* Vbase = g_V + (size_t)b * Sq * Hq;
        float4 kreg[4], vreg[4];
        #pragma unroll
        for (int it = 0; it < 4; it++) {
            int slot = tid + it * 256;
            int r = slot >> 4, c4 = slot & 15;
            kreg[it] = *(const float4*)&Kbase[(size_t)r * 64 + c4 * 4];
            vreg[it] = *(const float4*)&Vbase[(size_t)r * 64 + c4 * 4];
        }
        __syncthreads();   // Qs visible; smem from prev half fully read
        #pragma unroll
        for (int it = 0; it < 4; it++) {
            int slot = tid + it * 256;
            int r = slot >> 4, c4 = slot & 15;
            *(float4*)&Ks[r * 68 + c4 * 4] = kreg[it];
            *(float4*)&Vs[r * 68 + c4 * 4] = vreg[it];
        }
        __syncthreads();   // buffer 0 ready

        #pragma unroll 1
        for (int kt = 0; kt <= qt; kt++) {
            const int cur = kt & 1;
            const float* Kb = Ks + cur * 64 * 68;
            const float* Vb = Vs + cur * 64 * 68;

            // issue prefetch LDGs for next tile (consumed at iteration end)
            if (kt < qt) {
                const float* Kg = Kbase + (size_t)(kt + 1) * 64 * Hq;
                const float* Vg = Vbase + (size_t)(kt + 1) * 64 * Hq;
                #pragma unroll
                for (int it = 0; it < 4; it++) {
                    int slot = tid + it * 256;
                    int r = slot >> 4, c4 = slot & 15;
                    kreg[it] = *(const float4*)&Kg[(size_t)r * 64 + c4 * 4];
                    vreg[it] = *(const float4*)&Vg[(size_t)r * 64 + c4 * 4];
                }
            }

            // ---- S = Q K^T (FFMA2 paired along head dim) ----
            ull acc[4][4] = {};
            #pragma unroll 4
            for (int h = 0; h < 64; h += 4) {
                double2 qd[4], kd[4];
                #pragma unroll
                for (int i = 0; i < 4; i++)
                    qd[i] = *(const double2*)&Qs[(ty * 4 + i) * 68 + h];
                #pragma unroll
                for (int j = 0; j < 4; j++)
                    kd[j] = *(const double2*)&Kb[(tx * 4 + j) * 68 + h];
                #pragma unroll
                for (int i = 0; i < 4; i++)
                    #pragma unroll
                    for (int j = 0; j < 4; j++) {
                        ffma2(acc[i][j], (ull)__double_as_longlong(qd[i].x),
                                          (ull)__double_as_longlong(kd[j].x));
                        ffma2(acc[i][j], (ull)__double_as_longlong(qd[i].y),
                                          (ull)__double_as_longlong(kd[j].y));
                    }
            }

            // ---- register softmax (rows in parallel, 16-lane shfl groups) ----
            float fs[4];
            #pragma unroll
            for (int i = 0; i < 4; i++) {
                const int gi = qt * 64 + ty * 4 + i;
                float s[4];
                #pragma unroll
                for (int j = 0; j < 4; j++) {
                    int gj = kt * 64 + tx * 4 + j;
                    float sv = (lo2(acc[i][j]) + hi2(acc[i][j])) * 0.125f;
                    s[j] = (gj > gi) ? -1e30f : sv;
                }
                float mx = fmaxf(fmaxf(s[0], s[1]), fmaxf(s[2], s[3]));
                #pragma unroll
                for (int off = 8; off > 0; off >>= 1)
                    mx = fmaxf(mx, __shfl_xor_sync(0xffffffffu, mx, off));
                float mnew = fmaxf(m[i], mx);
                float p0 = __expf(s[0] - mnew);
                float p1 = __expf(s[1] - mnew);
                float p2 = __expf(s[2] - mnew);
                float p3 = __expf(s[3] - mnew);
                float ps = (p0 + p1) + (p2 + p3);
                #pragma unroll
                for (int off = 8; off > 0; off >>= 1)
                    ps += __shfl_xor_sync(0xffffffffu, ps, off);
                float f = __expf(m[i] - mnew);
                l[i] = l[i] * f + ps;
                m[i] = mnew;
                fs[i] = f;
                *(float4*)&Ps[(ty * 4 + i) * 68 + tx * 4] =
                    make_float4(p0, p1, p2, p3);
            }

            // rescale O (register-local, no sync needed)
            #pragma unroll
            for (int i = 0; i < 4; i++) {
                ull f2 = pack2(fs[i], fs[i]);
                o2[i][0] = fmul2(o2[i][0], f2);
                o2[i][1] = fmul2(o2[i][1], f2);
            }
            __syncthreads();   // SYNC1: Ps visible; prev readers of buffers done

            // ---- O += P V (float4 Ps, FFMA2 paired along H) ----
            #pragma unroll 4
            for (int j4 = 0; j4 < 16; j4++) {
                float4 pv[4];
                #pragma unroll
                for (int i = 0; i < 4; i++)
                    pv[i] = *(const float4*)&Ps[(ty * 4 + i) * 68 + j4 * 4];
                ull v2[4][2];
                #pragma unroll
                for (int jj = 0; jj < 4; jj++) {
                    double2 vv = *(const double2*)&Vb[(j4 * 4 + jj) * 68 + tx * 4];
                    v2[jj][0] = (ull)__double_as_longlong(vv.x);
                    v2[jj][1] = (ull)__double_as_longlong(vv.y);
                }
                #pragma unroll
                for (int i = 0; i < 4; i++) {
                    const float* pp = (const float*)&pv[i];
                    #pragma unroll
                    for (int jj = 0; jj < 4; jj++) {
                        ull p2 = pack2(pp[jj], pp[jj]);
                        ffma2(o2[i][0], p2, v2[jj][0]);
                        ffma2(o2[i][1], p2, v2[jj][1]);
                    }
                }
            }

            // store prefetched tile into the other buffer
            if (kt < qt) {
                float* Kn = Ks + (1 - cur) * 64 * 68;
                float* Vn = Vs + (1 - cur) * 64 * 68;
                #pragma unroll
                for (int it = 0; it < 4; it++) {
                    int slot = tid + it * 256;
                    int r = slot >> 4, c4 = slot & 15;
                    *(float4*)&Kn[r * 68 + c4 * 4] = kreg[it];
                    *(float4*)&Vn[r * 68 + c4 * 4] = vreg[it];
                }
            }
            __syncthreads();   // SYNC2: next buffer ready; Ps free for rewrite
        }

        // ---- epilogue: O /= l, write out ----
        #pragma unroll
        for (int i = 0; i < 4; i++) {
            int r = ty * 4 + i;
            float inv = 1.0f / l[i];
            float4 res;
            res.x = lo2(o2[i][0]) * inv;
            res.y = hi2(o2[i][0]) * inv;
            res.z = lo2(o2[i][1]) * inv;
            res.w = hi2(o2[i][1]) * inv;
            *(float4*)&out[((size_t)b * Sq + (size_t)qt * 64 + r) * Hq + tx * 4] = res;
        }
    }
}

// ============================================================================
extern "C" void kernel_launch(void* const* d_in, const int* in_sizes, int n_in,
                              void* d_out, int out_size)
{
    const float* x  = (const float*)d_in[0];
    const float* Wq = (const float*)d_in[1];
    const float* Wk = (const float*)d_in[2];
    const float* Wv = (const float*)d_in[3];
    float* out = (float*)d_out;

    const int attn_smem = 6 * 64 * 68 * (int)sizeof(float);  // 104448 B
    cudaFuncSetAttribute(attn_kernel, cudaFuncAttributeMaxDynamicSharedMemorySize,
                         attn_smem);

    qkv_kernel<<<dim3(128, 3), 256>>>(x, Wq, Wk, Wv);
    attn_kernel<<<dim3(32, 4), 256, attn_smem>>>(out);
}

// round 5
// speedup vs baseline: 1.6671x; 1.3527x over previous
#include <cuda_runtime.h>
#include <cstdint>

typedef unsigned long long ull;

#define Bq 4
#define Sq 4096
#define Eq 1024
#define Hq 64

// Scratch for projected Q, K, V (allocation-free rule: __device__ globals)
__device__ float g_Q[Bq * Sq * Hq];
__device__ float g_K[Bq * Sq * Hq];
__device__ float g_V[Bq * Sq * Hq];

// ---- packed f32x2 helpers (FFMA2 — ptxas never emits this from C++) ----
__device__ __forceinline__ void ffma2(ull& a, ull x, ull y) {
    asm("fma.rn.f32x2 %0, %1, %2, %0;" : "+l"(a) : "l"(x), "l"(y));
}
__device__ __forceinline__ ull fmul2(ull x, ull y) {
    ull r; asm("mul.rn.f32x2 %0, %1, %2;" : "=l"(r) : "l"(x), "l"(y)); return r;
}
__device__ __forceinline__ ull pack2(float lo, float hi) {
    ull r; asm("mov.b64 %0, {%1, %2};" : "=l"(r) : "f"(lo), "f"(hi)); return r;
}
__device__ __forceinline__ float lo2(ull v) { return __uint_as_float((unsigned)v); }
__device__ __forceinline__ float hi2(ull v) { return __uint_as_float((unsigned)(v >> 32)); }

// ---- cp.async helpers ----
__device__ __forceinline__ void cpasync16(uint32_t dst, const void* src) {
    asm volatile("cp.async.cg.shared.global [%0], [%1], 16;" :: "r"(dst), "l"(src));
}
__device__ __forceinline__ void cpasync_commit() {
    asm volatile("cp.async.commit_group;");
}
__device__ __forceinline__ void cpasync_wait0() {
    asm volatile("cp.async.wait_group 0;");
}

// XOR-swizzled tile addressing: 64x64 float tile, 16B chunks, chunk' = chunk ^ (row&15).
// Returns float index of the start of logical chunk `c4` (0..15) in row `r` (0..63).
__device__ __forceinline__ int SWADDR(int r, int c4) {
    return r * 64 + (((c4 ^ (r & 15)) << 2));
}

// ============================================================================
// Kernel 1: fused QKV projection GEMM (near SIMT fp32 floor; unchanged).
// ============================================================================
__global__ __launch_bounds__(256) void qkv_kernel(
    const float* __restrict__ x, const float* __restrict__ Wq,
    const float* __restrict__ Wk, const float* __restrict__ Wv)
{
    __shared__ float xs[32][132];   // [k][row]
    __shared__ float ws[32][64];    // [k][col]

    const int w = blockIdx.y;
    const float* W = (w == 0) ? Wq : (w == 1) ? Wk : Wv;
    float* out = (w == 0) ? g_Q : (w == 1) ? g_K : g_V;

    const int tid = threadIdx.x;
    const int tx = tid & 15;
    const int ty = tid >> 4;
    const int m0 = blockIdx.x * 128;

    ull acc[4][4] = {};

    for (int k0 = 0; k0 < Eq; k0 += 32) {
        #pragma unroll
        for (int it = 0; it < 4; it++) {
            int slot = tid + it * 256;
            int r = slot >> 3;
            int c4 = slot & 7;
            float4 v = *(const float4*)&x[(size_t)(m0 + r) * Eq + k0 + c4 * 4];
            xs[c4 * 4 + 0][r] = v.x;
            xs[c4 * 4 + 1][r] = v.y;
            xs[c4 * 4 + 2][r] = v.z;
            xs[c4 * 4 + 3][r] = v.w;
        }
        #pragma unroll
        for (int it = 0; it < 2; it++) {
            int slot = tid + it * 256;
            int r = slot >> 4;
            int c4 = slot & 15;
            *(float4*)&ws[r][c4 * 4] = *(const float4*)&W[(size_t)(k0 + r) * Hq + c4 * 4];
        }
        __syncthreads();

        #pragma unroll 8
        for (int kk = 0; kk < 32; kk++) {
            ull a2[4];
            #pragma unroll
            for (int i = 0; i < 4; i++)
                a2[i] = *(const ull*)&xs[kk][ty * 8 + 2 * i];
            float4 bv = *(const float4*)&ws[kk][tx * 4];
            ull b2[4] = { pack2(bv.x, bv.x), pack2(bv.y, bv.y),
                          pack2(bv.z, bv.z), pack2(bv.w, bv.w) };
            #pragma unroll
            for (int i = 0; i < 4; i++)
                #pragma unroll
                for (int j = 0; j < 4; j++)
                    ffma2(acc[i][j], a2[i], b2[j]);
        }
        __syncthreads();
    }

    #pragma unroll
    for (int i = 0; i < 4; i++) {
        int r = m0 + ty * 8 + 2 * i;
        float4 v0 = { lo2(acc[i][0]), lo2(acc[i][1]), lo2(acc[i][2]), lo2(acc[i][3]) };
        float4 v1 = { hi2(acc[i][0]), hi2(acc[i][1]), hi2(acc[i][2]), hi2(acc[i][3]) };
        *(float4*)&out[(size_t)r * Hq + tx * 4] = v0;
        *(float4*)&out[(size_t)(r + 1) * Hq + tx * 4] = v1;
    }
}

// ============================================================================
// Kernel 2: causal flash attention, fp32.
// R4: XOR-swizzled 64x64 tiles (bank-conflict floor), strided score-column
// ownership (thread tx owns cols {tx, tx+16, tx+32, tx+48}), cp.async K/V
// double-buffer prefetch, exp2-based softmax.
// 256 threads (16x16); block handles q-tiles qt and 63-qt (65 kv-iters).
// ============================================================================
__global__ __launch_bounds__(256, 1) void attn_kernel(float* __restrict__ out)
{
    extern __shared__ float sm[];
    float* Qs = sm;                    // 64x64 swizzled
    float* Ks = Qs + 4096;             // 2 x 64x64 (double buffer)
    float* Vs = Ks + 2 * 4096;         // 2 x 64x64
    float* Ps = Vs + 2 * 4096;         // 64x64

    const int tid  = threadIdx.x;
    const int tx   = tid & 15;         // owns score cols {tx + 16u}, O cols tx*4..+3
    const int ty   = tid >> 4;         // owns rows ty*4..+3
    const int b    = blockIdx.y;

    // smem byte addresses for cp.async
    const uint32_t s_Q = (uint32_t)__cvta_generic_to_shared(Qs);
    const uint32_t s_K = (uint32_t)__cvta_generic_to_shared(Ks);
    const uint32_t s_V = (uint32_t)__cvta_generic_to_shared(Vs);

    const int slot_r  = tid >> 4;        // base slot row (it adds 16 rows each)
    const int slot_c4 = tid & 15;

    #pragma unroll 1
    for (int half = 0; half < 2; half++) {
        const int qt = (half == 0) ? (int)blockIdx.x : 63 - (int)blockIdx.x;

        __syncthreads();   // previous half fully done with smem

        const float* Qg    = g_Q + ((size_t)b * Sq + (size_t)qt * 64) * Hq;
        const float* Kbase = g_K + (size_t)b * Sq * Hq;
        const float* Vbase = g_V + (size_t)b * Sq * Hq;

        // prologue: async-load Q tile + kv-tile 0 (buffer 0), swizzled dst
        #pragma unroll
        for (int it = 0; it < 4; it++) {
            int r = slot_r + it * 16;
            uint32_t off = (uint32_t)SWADDR(r, slot_c4) * 4u;
            const size_t g = (size_t)r * 64 + slot_c4 * 4;
            cpasync16(s_Q + off, Qg + g);
            cpasync16(s_K + off, Kbase + g);
            cpasync16(s_V + off, Vbase + g);
        }
        cpasync_commit();

        float m[4], l[4];
        #pragma unroll
        for (int i = 0; i < 4; i++) { m[i] = -1e30f; l[i] = 0.0f; }
        ull o2[4][2] = {};

        cpasync_wait0();
        __syncthreads();   // buffer 0 + Q ready

        #pragma unroll 1
        for (int kt = 0; kt <= qt; kt++) {
            const int cur = kt & 1;
            const float* Kb = Ks + cur * 4096;
            const float* Vb = Vs + cur * 4096;

            // prefetch next kv tile into alternate buffer via cp.async
            if (kt < qt) {
                const float* Kg = Kbase + (size_t)(kt + 1) * 64 * Hq;
                const float* Vg = Vbase + (size_t)(kt + 1) * 64 * Hq;
                const uint32_t boff = (uint32_t)(1 - cur) * 4096u * 4u;
                #pragma unroll
                for (int it = 0; it < 4; it++) {
                    int r = slot_r + it * 16;
                    uint32_t off = (uint32_t)SWADDR(r, slot_c4) * 4u;
                    const size_t g = (size_t)r * 64 + slot_c4 * 4;
                    cpasync16(s_K + boff + off, Kg + g);
                    cpasync16(s_V + boff + off, Vg + g);
                }
                cpasync_commit();
            }

            // ---- S = Q K^T (FFMA2 paired along head dim) ----
            ull acc[4][4] = {};    // [row i][col group u]
            #pragma unroll 4
            for (int h4 = 0; h4 < 16; h4++) {
                double2 qd[4], kd[4];
                #pragma unroll
                for (int i = 0; i < 4; i++)
                    qd[i] = *(const double2*)&Qs[SWADDR(ty * 4 + i, h4)];
                #pragma unroll
                for (int u = 0; u < 4; u++)
                    kd[u] = *(const double2*)&Kb[SWADDR(tx + 16 * u, h4)];
                #pragma unroll
                for (int i = 0; i < 4; i++)
                    #pragma unroll
                    for (int u = 0; u < 4; u++) {
                        ffma2(acc[i][u], (ull)__double_as_longlong(qd[i].x),
                                          (ull)__double_as_longlong(kd[u].x));
                        ffma2(acc[i][u], (ull)__double_as_longlong(qd[i].y),
                                          (ull)__double_as_longlong(kd[u].y));
                    }
            }

            // ---- register softmax (exp2-based; 16-lane shfl groups) ----
            const float SCL = 0.125f * 1.44269504089f;  // H^-0.5 * log2(e)
            float fs[4];
            #pragma unroll
            for (int i = 0; i < 4; i++) {
                const int gi = qt * 64 + ty * 4 + i;
                float s[4];
                #pragma unroll
                for (int u = 0; u < 4; u++) {
                    int gj = kt * 64 + tx + 16 * u;
                    float sv = (lo2(acc[i][u]) + hi2(acc[i][u])) * SCL;
                    s[u] = (gj > gi) ? -1e30f : sv;
                }
                float mx = fmaxf(fmaxf(s[0], s[1]), fmaxf(s[2], s[3]));
                #pragma unroll
                for (int off = 8; off > 0; off >>= 1)
                    mx = fmaxf(mx, __shfl_xor_sync(0xffffffffu, mx, off));
                float mnew = fmaxf(m[i], mx);
                float p[4];
                #pragma unroll
                for (int u = 0; u < 4; u++)
                    p[u] = exp2f(s[u] - mnew);
                float ps = (p[0] + p[1]) + (p[2] + p[3]);
                #pragma unroll
                for (int off = 8; off > 0; off >>= 1)
                    ps += __shfl_xor_sync(0xffffffffu, ps, off);
                float f = exp2f(m[i] - mnew);
                l[i] = l[i] * f + ps;
                m[i] = mnew;
                fs[i] = f;
                // scatter probs (strided cols): addr = row chunk (tx>>2)+4u, offset tx&3
                const int row = ty * 4 + i;
                #pragma unroll
                for (int u = 0; u < 4; u++)
                    Ps[SWADDR(row, (tx >> 2) + 4 * u) + (tx & 3)] = p[u];
            }

            // rescale O (register-local)
            #pragma unroll
            for (int i = 0; i < 4; i++) {
                ull f2 = pack2(fs[i], fs[i]);
                o2[i][0] = fmul2(o2[i][0], f2);
                o2[i][1] = fmul2(o2[i][1], f2);
            }
            __syncthreads();   // SYNC1: Ps visible

            // ---- O += P V (FFMA2 paired along H; thread owns h cols tx*4..+3) ----
            #pragma unroll 4
            for (int j4 = 0; j4 < 16; j4++) {
                float4 pv[4];
                #pragma unroll
                for (int i = 0; i < 4; i++)
                    pv[i] = *(const float4*)&Ps[SWADDR(ty * 4 + i, j4)];
                ull v2[4][2];
                #pragma unroll
                for (int jj = 0; jj < 4; jj++) {
                    double2 vv = *(const double2*)&Vb[SWADDR(j4 * 4 + jj, tx)];
                    v2[jj][0] = (ull)__double_as_longlong(vv.x);
                    v2[jj][1] = (ull)__double_as_longlong(vv.y);
                }
                #pragma unroll
                for (int i = 0; i < 4; i++) {
                    const float* pp = (const float*)&pv[i];
                    #pragma unroll
                    for (int jj = 0; jj < 4; jj++) {
                        ull p2 = pack2(pp[jj], pp[jj]);
                        ffma2(o2[i][0], p2, v2[jj][0]);
                        ffma2(o2[i][1], p2, v2[jj][1]);
                    }
                }
            }

            if (kt < qt) cpasync_wait0();
            __syncthreads();   // SYNC2: next buffer ready; Ps free
        }

        // ---- epilogue: O /= l, write out ----
        #pragma unroll
        for (int i = 0; i < 4; i++) {
            int r = ty * 4 + i;
            float inv = 1.0f / l[i];
            float4 res;
            res.x = lo2(o2[i][0]) * inv;
            res.y = hi2(o2[i][0]) * inv;
            res.z = lo2(o2[i][1]) * inv;
            res.w = hi2(o2[i][1]) * inv;
            *(float4*)&out[((size_t)b * Sq + (size_t)qt * 64 + r) * Hq + tx * 4] = res;
        }
    }
}

// ============================================================================
extern "C" void kernel_launch(void* const* d_in, const int* in_sizes, int n_in,
                              void* d_out, int out_size)
{
    const float* x  = (const float*)d_in[0];
    const float* Wq = (const float*)d_in[1];
    const float* Wk = (const float*)d_in[2];
    const float* Wv = (const float*)d_in[3];
    float* out = (float*)d_out;

    const int attn_smem = 6 * 4096 * (int)sizeof(float);  // 98304 B
    cudaFuncSetAttribute(attn_kernel, cudaFuncAttributeMaxDynamicSharedMemorySize,
                         attn_smem);

    qkv_kernel<<<dim3(128, 3), 256>>>(x, Wq, Wk, Wv);
    attn_kernel<<<dim3(32, 4), 256, attn_smem>>>(out);
}